// round 16
// baseline (speedup 1.0000x reference)
#include <cuda_runtime.h>
#include <cuda_bf16.h>
#include <stdint.h>
#include <math.h>

// ===== problem dims =====
#define Bdim 512
#define Tdim 256
#define Hdim 512
#define NCdim 512
#define SKELdim 256
#define GENdim 16

#define NBLK 128
#define NTHR 512

typedef unsigned long long ull;

// ===== persistent device state =====
__device__ float g_h1[2][Bdim * Hdim];
__device__ float g_h2[2][Bdim * Hdim];
__device__ ull   g_winner[2][Bdim];
__device__ unsigned g_key0[Tdim];
__device__ unsigned g_key1[Tdim];
__device__ unsigned g_bar_count;
__device__ volatile unsigned g_bar_gen;

// bf16 split activations [3][512][512] (ping-pong for h1/h2)
__device__ __align__(16) __nv_bfloat16 g_embsplit[3 * 262144];
__device__ __align__(16) __nv_bfloat16 g_h1s[2][3 * 262144];
__device__ __align__(16) __nv_bfloat16 g_h2s[2][3 * 262144];

// weight blobs
// layer (fused gi+gh tiles): [16 nt][192 vc][96 rows][32B]  (row = hl*3+g)
#define LBLOB (16 * 192 * 96 * 32)
__device__ __align__(16) unsigned char g_blob_ih1[LBLOB];
__device__ __align__(16) unsigned char g_blob_hh1[LBLOB];
__device__ __align__(16) unsigned char g_blob_ih2[LBLOB];
__device__ __align__(16) unsigned char g_blob_hh2[LBLOB];
// out: [8 nt][192 vc][64 rows][32B]
#define OBLOB (8 * 192 * 64 * 32)
__device__ __align__(16) unsigned char g_blob_out[OBLOB];

// ===== shared =====
// layer mainloop: sA 16KB + sB 24KB = 40KB ; layer epi 24KB ; out main 12KB ; out epi 32KB
__shared__ __align__(16) char smem_raw[41216];

// ===== helpers =====
__device__ __forceinline__ uint32_t smem_u32(const void* p) {
    uint32_t a;
    asm("{ .reg .u64 tmp; cvta.to.shared.u64 tmp, %1; cvt.u32.u64 %0, tmp; }" : "=r"(a) : "l"(p));
    return a;
}
__device__ __forceinline__ void ldsm4(uint32_t* r, uint32_t addr) {
    asm volatile("ldmatrix.sync.aligned.m8n8.x4.shared.b16 {%0,%1,%2,%3}, [%4];"
                 : "=r"(r[0]), "=r"(r[1]), "=r"(r[2]), "=r"(r[3]) : "r"(addr));
}
__device__ __forceinline__ void mma_bf16(float* c, const uint32_t* a, const uint32_t* b) {
    asm volatile("mma.sync.aligned.m16n8k16.row.col.f32.bf16.bf16.f32 "
                 "{%0,%1,%2,%3}, {%4,%5,%6,%7}, {%8,%9}, {%0,%1,%2,%3};"
                 : "+f"(c[0]), "+f"(c[1]), "+f"(c[2]), "+f"(c[3])
                 : "r"(a[0]), "r"(a[1]), "r"(a[2]), "r"(a[3]), "r"(b[0]), "r"(b[1]));
}
__device__ __forceinline__ void split3(float x, __nv_bfloat16& b0, __nv_bfloat16& b1, __nv_bfloat16& b2) {
    b0 = __float2bfloat16_rn(x);
    float r1 = x - __bfloat162float(b0);
    b1 = __float2bfloat16_rn(r1);
    b2 = __float2bfloat16_rn(r1 - __bfloat162float(b1));
}
__device__ __forceinline__ int PA_of(int p) { return (p == 2 || p == 3) ? 1 : (p == 5 ? 2 : 0); }
__device__ __forceinline__ uint32_t fkey(float v) {
    uint32_t u = __float_as_uint(v);
    return (u & 0x80000000u) ? ~u : (u | 0x80000000u);
}
__device__ __forceinline__ int win_decode(ull w) { return 511 - (int)(w & 511ull); }

// ===== threefry2x32 =====
__device__ __forceinline__ void threefry2x32(unsigned k0, unsigned k1,
                                             unsigned c0, unsigned c1,
                                             unsigned& o0, unsigned& o1) {
    unsigned ks2 = k0 ^ k1 ^ 0x1BD11BDAu;
    unsigned x0 = c0 + k0;
    unsigned x1 = c1 + k1;
#define TF_RND(r) { x0 += x1; x1 = (x1 << (r)) | (x1 >> (32 - (r))); x1 ^= x0; }
    TF_RND(13) TF_RND(15) TF_RND(26) TF_RND(6)
    x0 += k1;  x1 += ks2 + 1u;
    TF_RND(17) TF_RND(29) TF_RND(16) TF_RND(24)
    x0 += ks2; x1 += k0 + 2u;
    TF_RND(13) TF_RND(15) TF_RND(26) TF_RND(6)
    x0 += k0;  x1 += k1 + 3u;
    TF_RND(17) TF_RND(29) TF_RND(16) TF_RND(24)
    x0 += k1;  x1 += ks2 + 4u;
    TF_RND(13) TF_RND(15) TF_RND(26) TF_RND(6)
    x0 += ks2; x1 += k0 + 5u;
#undef TF_RND
    o0 = x0; o1 = x1;
}
__device__ __forceinline__ float gumbel_of(unsigned key0, unsigned key1, unsigned j) {
    unsigned o0, o1;
    threefry2x32(key0, key1, 0u, j, o0, o1);
    unsigned bits = o0 ^ o1;
    const float tiny = 1.17549435e-38f;
    float f = __uint_as_float((bits >> 9) | 0x3F800000u) - 1.0f;
    float u = fmaxf(tiny, f + tiny);
    return -logf(-logf(u));
}

// ===== software grid barrier =====
__device__ __forceinline__ void grid_barrier() {
    __syncthreads();
    if (threadIdx.x == 0) {
        __threadfence();
        unsigned gen = g_bar_gen;
        if (atomicAdd(&g_bar_count, 1u) == NBLK - 1) {
            atomicExch(&g_bar_count, 0u);
            __threadfence();
            g_bar_gen = gen + 1u;
        } else {
            while (g_bar_gen == gen) __nanosleep(32);
        }
        __threadfence();
    }
    __syncthreads();
}

// ===== blob packing =====
__device__ void pack_blob_fused(const float* __restrict__ W, unsigned char* __restrict__ blob,
                                int gt, int gN) {
    const int PBv[6] = {0, 1, 0, 1, 2, 0};
    for (int u = gt; u < 1536 * 32; u += gN) {
        int nw = u >> 5, kc = u & 31;
        const float* wp = W + (size_t)nw * 512 + kc * 16;
        __align__(16) __nv_bfloat16 sp[3][16];
        #pragma unroll
        for (int i = 0; i < 16; i++) split3(wp[i], sp[0][i], sp[1][i], sp[2][i]);
        int g = nw >> 9, h = nw & 511, nt = h >> 5, hl = h & 31;
        int pr = hl * 3 + g;
        #pragma unroll
        for (int p = 0; p < 6; p++) {
            int vc = p * 32 + kc;
            unsigned char* d = blob + ((size_t)(nt * 192 + vc) * 96 + pr) * 32;
            const uint4* s4 = reinterpret_cast<const uint4*>(sp[PBv[p]]);
            *reinterpret_cast<uint4*>(d)      = s4[0];
            *reinterpret_cast<uint4*>(d + 16) = s4[1];
        }
    }
}
__device__ void pack_blob_out(const float* __restrict__ W, unsigned char* __restrict__ blob,
                              int gt, int gN) {
    const int PBv[6] = {0, 1, 0, 1, 2, 0};
    for (int u = gt; u < 512 * 32; u += gN) {
        int n = u >> 5, kc = u & 31;
        const float* wp = W + (size_t)n * 512 + kc * 16;
        __align__(16) __nv_bfloat16 sp[3][16];
        #pragma unroll
        for (int i = 0; i < 16; i++) split3(wp[i], sp[0][i], sp[1][i], sp[2][i]);
        int nt = n >> 6, nl = n & 63;
        #pragma unroll
        for (int p = 0; p < 6; p++) {
            int vc = p * 32 + kc;
            unsigned char* d = blob + ((size_t)(nt * 192 + vc) * 64 + nl) * 32;
            const uint4* s4 = reinterpret_cast<const uint4*>(sp[PBv[p]]);
            *reinterpret_cast<uint4*>(d)      = s4[0];
            *reinterpret_cast<uint4*>(d + 16) = s4[1];
        }
    }
}

// ===== fused layer stage: dual gemm (gi,gh) 64m x 96n, warp 32m x 48n, k-split 2 =====
__device__ void layer_stage(const __nv_bfloat16* __restrict__ Ax, bool useWin, int slot,
                            const __nv_bfloat16* __restrict__ Ah,
                            const unsigned char* __restrict__ Bi,
                            const unsigned char* __restrict__ Bh,
                            const float* __restrict__ bih, const float* __restrict__ bhh,
                            const float* __restrict__ Hprev, float* __restrict__ Hout,
                            __nv_bfloat16* __restrict__ Hsplit) {
    const int tid = threadIdx.x, bx = blockIdx.x;
    const int mt = bx >> 4, nt = bx & 15;
    const int m0 = mt * 64;
    __nv_bfloat16* sA = (__nv_bfloat16*)smem_raw;             // [2 buf][2 role][64][32]
    __nv_bfloat16* sB = (__nv_bfloat16*)(smem_raw + 16384);   // [2 buf][2 role][96][32]

    const int warp = tid >> 5, lane = tid & 31;
    const int role = warp >> 3;            // 0: gi, 1: gh
    const int w8 = warp & 7;
    const int mpart = w8 >> 2;             // 0..1 (32m each)
    const int npart = (w8 >> 1) & 1;       // 0..1 (48n each)
    const int ks = w8 & 1;                 // vb parity

    // ---- loaders (identical to R12) ----
    const int roleA = tid >> 8, rowA = (tid >> 2) & 63, kuA = tid & 3;
    const __nv_bfloat16* aBase;
    if (roleA == 0) {
        int m = m0 + rowA;
        int tok = useWin ? win_decode(g_winner[slot][m]) : 0;
        aBase = useWin ? (Ax + (size_t)tok * 512) : (Ax + (size_t)m * 512);
    } else {
        aBase = Ah + (size_t)(m0 + rowA) * 512;
    }
    const int aSt = roleA * 2048 + rowA * 32 + ((kuA ^ ((rowA >> 1) & 3)) * 8);
    const int roleB1 = (tid >= 384) ? 1 : 0;
    const int rv1 = tid - roleB1 * 384;
    const int rowB1 = rv1 >> 2, kuB1 = rv1 & 3;
    const unsigned char* bBase1 = (roleB1 ? Bh : Bi) + (size_t)nt * 192 * 3072;
    const int bSt1 = roleB1 * 3072 + rowB1 * 32 + ((kuB1 ^ ((rowB1 >> 1) & 3)) * 8);
    const bool hasU2 = (tid < 256);
    const int rv2 = tid + 128;
    const int rowB2 = rv2 >> 2, kuB2 = rv2 & 3;
    const unsigned char* bBase2 = Bh + (size_t)nt * 192 * 3072;
    const int bSt2 = 3072 + rowB2 * 32 + ((kuB2 ^ ((rowB2 >> 1) & 3)) * 8);

    float acc[2][6][4];
    #pragma unroll
    for (int mi = 0; mi < 2; mi++)
        #pragma unroll
        for (int j = 0; j < 6; j++)
            #pragma unroll
            for (int q = 0; q < 4; q++) acc[mi][j][q] = 0.f;

    uint32_t sAu = smem_u32(sA), sBu = smem_u32(sB);
    const int ar = mpart * 32 + (lane & 15);
    const int a_half = lane >> 4;
    const int br_base = npart * 48 + (lane & 7) + ((lane >> 4) << 3);
    const int b_half = (lane >> 3) & 1;

    uint4 pf0, pf1, pf2;
    {   // prologue vb=0
        int vcA = (kuA >> 1);
        int sA3 = PA_of(vcA >> 5);
        pf0 = *reinterpret_cast<const uint4*>(aBase + sA3 * 262144 + (vcA & 31) * 16 + (kuA & 1) * 8);
        int vc1 = (kuB1 >> 1);
        pf1 = *reinterpret_cast<const uint4*>(bBase1 + (size_t)vc1 * 3072 + rowB1 * 32 + (kuB1 & 1) * 16);
        if (hasU2) {
            int vc2 = (kuB2 >> 1);
            pf2 = *reinterpret_cast<const uint4*>(bBase2 + (size_t)vc2 * 3072 + rowB2 * 32 + (kuB2 & 1) * 16);
        }
    }

    #pragma unroll 2
    for (int vb = 0; vb < 96; vb++) {
        const int buf = vb & 1;
        *reinterpret_cast<uint4*>(sA + buf * 4096 + aSt) = pf0;
        *reinterpret_cast<uint4*>(sB + buf * 6144 + bSt1) = pf1;
        if (hasU2) *reinterpret_cast<uint4*>(sB + buf * 6144 + bSt2) = pf2;
        __syncthreads();

        if (vb + 1 < 96) {
            int vn = (vb + 1) * 2;
            int vcA = vn + (kuA >> 1);
            int sA3 = PA_of(vcA >> 5);
            pf0 = *reinterpret_cast<const uint4*>(aBase + sA3 * 262144 + (vcA & 31) * 16 + (kuA & 1) * 8);
            int vc1 = vn + (kuB1 >> 1);
            pf1 = *reinterpret_cast<const uint4*>(bBase1 + (size_t)vc1 * 3072 + rowB1 * 32 + (kuB1 & 1) * 16);
            if (hasU2) {
                int vc2 = vn + (kuB2 >> 1);
                pf2 = *reinterpret_cast<const uint4*>(bBase2 + (size_t)vc2 * 3072 + rowB2 * 32 + (kuB2 & 1) * 16);
            }
        }

        if ((vb & 1) == ks) {
            #pragma unroll
            for (int kc2 = 0; kc2 < 2; kc2++) {
                uint32_t aF[2][4];
                #pragma unroll
                for (int mi = 0; mi < 2; mi++) {
                    int rowa = ar + mi * 16;
                    int ua = kc2 * 2 + a_half;
                    int up = ua ^ ((rowa >> 1) & 3);
                    ldsm4(aF[mi], sAu + (buf * 4096 + role * 2048 + rowa * 32 + up * 8) * 2);
                }
                uint32_t bF[3][4];
                #pragma unroll
                for (int bt = 0; bt < 3; bt++) {
                    int rb = br_base + bt * 16;
                    int ub = kc2 * 2 + b_half;
                    int up = ub ^ ((rb >> 1) & 3);
                    ldsm4(bF[bt], sBu + (buf * 6144 + role * 3072 + rb * 32 + up * 8) * 2);
                }
                #pragma unroll
                for (int mi = 0; mi < 2; mi++)
                    #pragma unroll
                    for (int bt = 0; bt < 3; bt++) {
                        mma_bf16(acc[mi][bt * 2 + 0], aF[mi], &bF[bt][0]);
                        mma_bf16(acc[mi][bt * 2 + 1], aF[mi], &bF[bt][2]);
                    }
            }
        }
    }

    // ---- epilogue: 4 phases of 16m; reduce k-split partials + combine ----
    float* stg = (float*)smem_raw;   // [2 role][2 ks][16 m][96] = 24KB
    #pragma unroll 1
    for (int ph = 0; ph < 4; ph++) {
        __syncthreads();
        if (mpart == (ph >> 1)) {
            const int mi = ph & 1;
            int ml = lane >> 2;
            #pragma unroll
            for (int j = 0; j < 6; j++) {
                int col = npart * 48 + j * 8 + (lane & 3) * 2;
                float* base = stg + ((role * 2 + ks) * 16) * 96;
                base[ml * 96 + col]     = acc[mi][j][0];
                base[ml * 96 + col + 1] = acc[mi][j][1];
                base[(ml + 8) * 96 + col]     = acc[mi][j][2];
                base[(ml + 8) * 96 + col + 1] = acc[mi][j][3];
            }
        }
        __syncthreads();
        {
            int ml = tid >> 5, hl = tid & 31;
            int m = m0 + ph * 16 + ml;
            int h = nt * 32 + hl;
            const float* r0 = stg + (0 * 16 + ml) * 96 + hl * 3;   // role0 ks0
            const float* r1 = stg + (1 * 16 + ml) * 96 + hl * 3;   // role0 ks1
            const float* r2 = stg + (2 * 16 + ml) * 96 + hl * 3;   // role1 ks0
            const float* r3 = stg + (3 * 16 + ml) * 96 + hl * 3;   // role1 ks1
            float ir  = (r0[0] + r1[0]) + bih[h];
            float iz  = (r0[1] + r1[1]) + bih[512 + h];
            float in_ = (r0[2] + r1[2]) + bih[1024 + h];
            float hr  = (r2[0] + r3[0]) + bhh[h];
            float hz  = (r2[1] + r3[1]) + bhh[512 + h];
            float hn  = (r2[2] + r3[2]) + bhh[1024 + h];
            float r = 1.f / (1.f + expf(-(ir + hr)));
            float z = 1.f / (1.f + expf(-(iz + hz)));
            float n = tanhf(in_ + r * hn);
            float hout = (1.f - z) * n + z * Hprev[(size_t)m * 512 + h];
            Hout[(size_t)m * 512 + h] = hout;
            __nv_bfloat16 s0, s1, s2;
            split3(hout, s0, s1, s2);
            int idx = m * 512 + h;
            Hsplit[idx] = s0;
            Hsplit[262144 + idx] = s1;
            Hsplit[2 * 262144 + idx] = s2;
        }
    }
    __syncthreads();
}

// ===== out stage: 32m x 64n, warp 32m x 16n, k-split 4 =====
__device__ void out_stage(const __nv_bfloat16* __restrict__ Abase,
                          const float* __restrict__ bout,
                          float* __restrict__ out, int t, int wslot) {
    const int tid = threadIdx.x, bx = blockIdx.x;
    const int warp = tid >> 5, lane = tid & 31;
    const int ks = warp >> 2;              // 0..3 (vb mod 4)
    const int npart = warp & 3;            // 0..3 (16n each)
    const int omt = bx >> 3, ont = bx & 7;
    const int m0 = omt * 32, n0 = ont * 64;
    __nv_bfloat16* sA = (__nv_bfloat16*)smem_raw;            // [2][32][32]
    __nv_bfloat16* sB = (__nv_bfloat16*)(smem_raw + 4096);   // [2][64][32]

    const unsigned char* bBase = g_blob_out + (size_t)ont * 192 * 2048;

    const bool ldA = (tid < 128);
    const bool ldB = (!ldA && tid < 384);
    int l0r = 0, l0u = 0;
    const __nv_bfloat16* aSrc = nullptr;
    if (ldA) {
        l0r = tid >> 2; l0u = tid & 3;
        aSrc = Abase + (size_t)(m0 + l0r) * 512;
    } else if (ldB) {
        int bu = tid - 128; l0r = bu >> 2; l0u = bu & 3;
    }
    const int st0 = l0r * 32 + ((l0u ^ ((l0r >> 1) & 3)) * 8);

    float acc[2][2][4];
    #pragma unroll
    for (int mi = 0; mi < 2; mi++)
        #pragma unroll
        for (int nj = 0; nj < 2; nj++)
            #pragma unroll
            for (int q = 0; q < 4; q++) acc[mi][nj][q] = 0.f;

    uint32_t sAu = smem_u32(sA), sBu = smem_u32(sB);
    const int ar = lane & 15;
    const int a_half = lane >> 4;
    const int brb = npart * 16 + (lane & 7) + ((lane >> 4) << 3);
    const int b_half = (lane >> 3) & 1;

    uint4 pf0;
    {
        int vc = (l0u >> 1);
        if (ldA) {
            int s = PA_of(vc >> 5);
            pf0 = *reinterpret_cast<const uint4*>(aSrc + s * 262144 + (vc & 31) * 16 + (l0u & 1) * 8);
        } else if (ldB) {
            pf0 = *reinterpret_cast<const uint4*>(bBase + (size_t)vc * 2048 + l0r * 32 + (l0u & 1) * 16);
        }
    }

    #pragma unroll 4
    for (int vb = 0; vb < 96; vb++) {
        const int buf = vb & 1;
        if (ldA) *reinterpret_cast<uint4*>(sA + buf * 1024 + st0) = pf0;
        else if (ldB) *reinterpret_cast<uint4*>(sB + buf * 2048 + st0) = pf0;
        __syncthreads();

        if (vb + 1 < 96) {
            int vn = (vb + 1) * 2;
            int vc = vn + (l0u >> 1);
            if (ldA) {
                int s = PA_of(vc >> 5);
                pf0 = *reinterpret_cast<const uint4*>(aSrc + s * 262144 + (vc & 31) * 16 + (l0u & 1) * 8);
            } else if (ldB) {
                pf0 = *reinterpret_cast<const uint4*>(bBase + (size_t)vc * 2048 + l0r * 32 + (l0u & 1) * 16);
            }
        }

        if ((vb & 3) == ks) {
            #pragma unroll
            for (int kc2 = 0; kc2 < 2; kc2++) {
                uint32_t aF[2][4];
                #pragma unroll
                for (int mi = 0; mi < 2; mi++) {
                    int rowa = ar + mi * 16;
                    int ua = kc2 * 2 + a_half;
                    int up = ua ^ ((rowa >> 1) & 3);
                    ldsm4(aF[mi], sAu + (buf * 1024 + rowa * 32 + up * 8) * 2);
                }
                uint32_t bF[4];
                {
                    int ub = kc2 * 2 + b_half;
                    int up = ub ^ ((brb >> 1) & 3);
                    ldsm4(bF, sBu + (buf * 2048 + brb * 32 + up * 8) * 2);
                }
                #pragma unroll
                for (int mi = 0; mi < 2; mi++) {
                    mma_bf16(acc[mi][0], aF[mi], &bF[0]);
                    mma_bf16(acc[mi][1], aF[mi], &bF[2]);
                }
            }
        }
    }

    // ---- epilogue: reduce 4 k-partials, bias, logits, gumbel argmax ----
    float* stg = (float*)smem_raw;   // [4 ks][32 m][64 n] = 32KB
    __syncthreads();
    {
        float* base = stg + (ks * 32) * 64;
        #pragma unroll
        for (int mi = 0; mi < 2; mi++) {
            int r = mi * 16 + (lane >> 2);
            #pragma unroll
            for (int nj = 0; nj < 2; nj++) {
                int cl = npart * 16 + nj * 8 + (lane & 3) * 2;
                base[r * 64 + cl]     = acc[mi][nj][0];
                base[r * 64 + cl + 1] = acc[mi][nj][1];
                base[(r + 8) * 64 + cl]     = acc[mi][nj][2];
                base[(r + 8) * 64 + cl + 1] = acc[mi][nj][3];
            }
        }
    }
    __syncthreads();
    unsigned key0 = g_key0[t], key1 = g_key1[t];
    #pragma unroll
    for (int q = 0; q < 4; q++) {
        int e = tid + q * 512;
        int r = e >> 6, cl = e & 63;
        float v = ((stg[(0 * 32 + r) * 64 + cl] + stg[(1 * 32 + r) * 64 + cl])
                 + stg[(2 * 32 + r) * 64 + cl]) + stg[(3 * 32 + r) * 64 + cl];
        v += bout[n0 + cl];
        int m = m0 + r;
        out[(size_t)m * (Tdim * NCdim) + (size_t)t * NCdim + n0 + cl] = v;
        float g = v + gumbel_of(key0, key1, (unsigned)(m * 512 + n0 + cl));
        ull kr = ((ull)fkey(g) << 32) | (ull)(511 - (n0 + cl));
        #pragma unroll
        for (int o = 1; o <= 16; o <<= 1) {
            ull other = __shfl_xor_sync(0xffffffffu, kr, o);
            if (other > kr) kr = other;
        }
        if ((lane & 31) == 0) atomicMax(&g_winner[wslot][m], kr);
    }
    __syncthreads();
}

// ===== main persistent kernel =====
__global__ void __launch_bounds__(NTHR, 1)
prior_mma(const float* __restrict__ note, const float* __restrict__ genre,
          const float* __restrict__ Whid, const float* __restrict__ bhid,
          const float* __restrict__ emb,
          const float* __restrict__ Wih1, const float* __restrict__ Whh1,
          const float* __restrict__ bih1, const float* __restrict__ bhh1,
          const float* __restrict__ Wih2, const float* __restrict__ Whh2,
          const float* __restrict__ bih2, const float* __restrict__ bhh2,
          const float* __restrict__ Wout, const float* __restrict__ bout,
          float* __restrict__ out, float* __restrict__ tokout) {
    const int tid = threadIdx.x, bx = blockIdx.x;
    const int gt = bx * NTHR + tid;
    const int gN = NBLK * NTHR;

    // ---------- init ----------
    {
        if (gt < Tdim) {
            unsigned o0, o1;
            threefry2x32(0u, 42u, 0u, (unsigned)gt, o0, o1);
            g_key0[gt] = o0; g_key1[gt] = o1;
        }
        if (gt < Bdim) {
            g_winner[0][gt] = 0ull;
            g_winner[1][gt] = 511ull;   // decodes to tok=0 for step 0
        }

        pack_blob_fused(Wih1, g_blob_ih1, gt, gN);
        pack_blob_fused(Whh1, g_blob_hh1, gt, gN);
        pack_blob_fused(Wih2, g_blob_ih2, gt, gN);
        pack_blob_fused(Whh2, g_blob_hh2, gt, gN);
        pack_blob_out(Wout, g_blob_out, gt, gN);

        for (int idx = gt; idx < 262144; idx += gN) {
            __nv_bfloat16 s0, s1, s2;
            split3(emb[idx], s0, s1, s2);
            g_embsplit[idx] = s0;
            g_embsplit[262144 + idx] = s1;
            g_embsplit[2 * 262144 + idx] = s2;
        }

        float* sInit = (float*)smem_raw;
        for (int r = 0; r < Bdim / NBLK; r++) {
            int b = bx * (Bdim / NBLK) + r;
            for (int i = tid; i < SKELdim; i += NTHR) sInit[i] = note[b * SKELdim + i];
            for (int i = tid; i < GENdim; i += NTHR) sInit[SKELdim + i] = genre[b * GENdim + i];
            __syncthreads();
            for (int j = tid; j < Hdim; j += NTHR) {
                const float* w = Whid + (size_t)j * (SKELdim + GENdim);
                float acc = 0.f;
                #pragma unroll 8
                for (int k = 0; k < SKELdim + GENdim; k++) acc = fmaf(sInit[k], w[k], acc);
                acc += bhid[j];
                int idx = b * Hdim + j;
                g_h1[0][idx] = acc;
                __nv_bfloat16 s0, s1, s2;
                split3(acc, s0, s1, s2);
                g_h1s[0][idx] = s0;
                g_h1s[0][262144 + idx] = s1;
                g_h1s[0][2 * 262144 + idx] = s2;
            }
            __syncthreads();
        }
    }
    grid_barrier();

    for (int t = 0; t < Tdim; t++) {
        const int rp = t & 1, wp = rp ^ 1;
        const int rslot = (t + 1) & 1;   // winner slot holding sample of step t-1

        if (t > 0 && bx == 0 && tokout) {
            tokout[(size_t)tid * Tdim + (t - 1)] = (float)win_decode(g_winner[rslot][tid]);
        }

        // ---- stage 1: layer1 dual gemm + combine -> h1[wp] ----
        layer_stage(g_embsplit, true, rslot,
                    g_h1s[rp], g_blob_ih1, g_blob_hh1,
                    bih1, bhh1, g_h1[rp], g_h1[wp], g_h1s[wp]);
        grid_barrier();

        // ---- stage 2: layer2 dual gemm + combine -> h2[wp] (+ winner slot reset) ----
        if (bx == 1 && tid < 512) g_winner[rslot][tid] = 0ull;
        layer_stage(g_h1s[wp], false, 0,
                    (t == 0) ? g_h1s[wp] : g_h2s[rp],
                    g_blob_ih2, g_blob_hh2,
                    bih2, bhh2,
                    (t == 0) ? g_h1[wp] : g_h2[rp],
                    g_h2[wp], g_h2s[wp]);
        grid_barrier();

        // ---- stage 3: out gemm + gumbel argmax -> winner[t&1] ----
        out_stage(g_h2s[wp], bout, out, t, t & 1);
        grid_barrier();
    }

    if (bx == 0 && tokout) {
        tokout[(size_t)tid * Tdim + (Tdim - 1)] = (float)win_decode(g_winner[1][tid]);
    }
}

// ===== launch: ONE graph node =====
extern "C" void kernel_launch(void* const* d_in, const int* in_sizes, int n_in,
                              void* d_out, int out_size) {
    const float* note  = (const float*)d_in[1];
    const float* genre = (const float*)d_in[2];
    const float* W_hid = (const float*)d_in[3];
    const float* b_hid = (const float*)d_in[4];
    const float* emb   = (const float*)d_in[5];
    const float* W_ih1 = (const float*)d_in[6];
    const float* W_hh1 = (const float*)d_in[7];
    const float* b_ih1 = (const float*)d_in[8];
    const float* b_hh1 = (const float*)d_in[9];
    const float* W_ih2 = (const float*)d_in[10];
    const float* W_hh2 = (const float*)d_in[11];
    const float* b_ih2 = (const float*)d_in[12];
    const float* b_hh2 = (const float*)d_in[13];
    const float* W_out = (const float*)d_in[14];
    const float* b_out = (const float*)d_in[15];

    float* out = (float*)d_out;
    const long long need = (long long)Bdim * Tdim * NCdim + (long long)Bdim * Tdim;
    float* tokout = ((long long)out_size >= need) ? (out + (size_t)Bdim * Tdim * NCdim) : nullptr;

    prior_mma<<<NBLK, NTHR>>>(note, genre, W_hid, b_hid, emb,
                              W_ih1, W_hh1, b_ih1, b_hh1,
                              W_ih2, W_hh2, b_ih2, b_hh2,
                              W_out, b_out, out, tokout);
}

// round 17
// speedup vs baseline: 2.6976x; 2.6976x over previous
#include <cuda_runtime.h>
#include <cuda_bf16.h>
#include <stdint.h>
#include <math.h>

// ===== problem dims =====
#define Bdim 512
#define Tdim 256
#define Hdim 512
#define NCdim 512
#define SKELdim 256
#define GENdim 16

#define NBLK 128
#define NTHR 512

// 4-term double-bf16: products (A,B) = (0,0),(0,1),(1,0),(1,1); virtual K = 2048
#define NVC 128     // virtual k-chunks of 16
#define NVB 64      // mainloop iterations (2 vc each)
#define PLANE 262144

typedef unsigned long long ull;

// ===== persistent device state =====
__device__ float g_h1[2][Bdim * Hdim];
__device__ float g_h2[2][Bdim * Hdim];
__device__ ull   g_winner[2][Bdim];
__device__ unsigned g_key0[Tdim];
__device__ unsigned g_key1[Tdim];
__device__ unsigned g_bar_count;
__device__ volatile unsigned g_bar_gen;

// bf16 split activations [2 planes][512*512] (ping-pong for h1/h2)
__device__ __align__(16) __nv_bfloat16 g_embsplit[2 * PLANE];
__device__ __align__(16) __nv_bfloat16 g_h1s[2][2 * PLANE];
__device__ __align__(16) __nv_bfloat16 g_h2s[2][2 * PLANE];

// weight blobs
// layer (fused gi+gh tiles): [16 nt][128 vc][96 rows][32B]  (row = hl*3+g)
#define LBLOB (16 * NVC * 96 * 32)
__device__ __align__(16) unsigned char g_blob_ih1[LBLOB];
__device__ __align__(16) unsigned char g_blob_hh1[LBLOB];
__device__ __align__(16) unsigned char g_blob_ih2[LBLOB];
__device__ __align__(16) unsigned char g_blob_hh2[LBLOB];
// out: [8 nt][128 vc][64 rows][32B]
#define OBLOB (8 * NVC * 64 * 32)
__device__ __align__(16) unsigned char g_blob_out[OBLOB];

// ===== shared =====
__shared__ __align__(16) char smem_raw[41216];

// ===== helpers =====
__device__ __forceinline__ uint32_t smem_u32(const void* p) {
    uint32_t a;
    asm("{ .reg .u64 tmp; cvta.to.shared.u64 tmp, %1; cvt.u32.u64 %0, tmp; }" : "=r"(a) : "l"(p));
    return a;
}
__device__ __forceinline__ void ldsm4(uint32_t* r, uint32_t addr) {
    asm volatile("ldmatrix.sync.aligned.m8n8.x4.shared.b16 {%0,%1,%2,%3}, [%4];"
                 : "=r"(r[0]), "=r"(r[1]), "=r"(r[2]), "=r"(r[3]) : "r"(addr));
}
__device__ __forceinline__ void ldsm2(uint32_t* r, uint32_t addr) {
    asm volatile("ldmatrix.sync.aligned.m8n8.x2.shared.b16 {%0,%1}, [%2];"
                 : "=r"(r[0]), "=r"(r[1]) : "r"(addr));
}
__device__ __forceinline__ void mma_bf16(float* c, const uint32_t* a, const uint32_t* b) {
    asm volatile("mma.sync.aligned.m16n8k16.row.col.f32.bf16.bf16.f32 "
                 "{%0,%1,%2,%3}, {%4,%5,%6,%7}, {%8,%9}, {%0,%1,%2,%3};"
                 : "+f"(c[0]), "+f"(c[1]), "+f"(c[2]), "+f"(c[3])
                 : "r"(a[0]), "r"(a[1]), "r"(a[2]), "r"(a[3]), "r"(b[0]), "r"(b[1]));
}
__device__ __forceinline__ void split2(float x, __nv_bfloat16& b0, __nv_bfloat16& b1) {
    b0 = __float2bfloat16_rn(x);
    b1 = __float2bfloat16_rn(x - __bfloat162float(b0));
}
// product p -> A split: (0,0),(0,1),(1,0),(1,1)
__device__ __forceinline__ int PA_of(int p) { return p >> 1; }
__device__ __forceinline__ uint32_t fkey(float v) {
    uint32_t u = __float_as_uint(v);
    return (u & 0x80000000u) ? ~u : (u | 0x80000000u);
}
__device__ __forceinline__ int win_decode(ull w) { return 511 - (int)(w & 511ull); }

// ===== threefry2x32 =====
__device__ __forceinline__ void threefry2x32(unsigned k0, unsigned k1,
                                             unsigned c0, unsigned c1,
                                             unsigned& o0, unsigned& o1) {
    unsigned ks2 = k0 ^ k1 ^ 0x1BD11BDAu;
    unsigned x0 = c0 + k0;
    unsigned x1 = c1 + k1;
#define TF_RND(r) { x0 += x1; x1 = (x1 << (r)) | (x1 >> (32 - (r))); x1 ^= x0; }
    TF_RND(13) TF_RND(15) TF_RND(26) TF_RND(6)
    x0 += k1;  x1 += ks2 + 1u;
    TF_RND(17) TF_RND(29) TF_RND(16) TF_RND(24)
    x0 += ks2; x1 += k0 + 2u;
    TF_RND(13) TF_RND(15) TF_RND(26) TF_RND(6)
    x0 += k0;  x1 += k1 + 3u;
    TF_RND(17) TF_RND(29) TF_RND(16) TF_RND(24)
    x0 += k1;  x1 += ks2 + 4u;
    TF_RND(13) TF_RND(15) TF_RND(26) TF_RND(6)
    x0 += ks2; x1 += k0 + 5u;
#undef TF_RND
    o0 = x0; o1 = x1;
}
__device__ __forceinline__ float gumbel_of(unsigned key0, unsigned key1, unsigned j) {
    unsigned o0, o1;
    threefry2x32(key0, key1, 0u, j, o0, o1);
    unsigned bits = o0 ^ o1;
    const float tiny = 1.17549435e-38f;
    float f = __uint_as_float((bits >> 9) | 0x3F800000u) - 1.0f;
    float u = fmaxf(tiny, f + tiny);
    return -logf(-logf(u));
}

// ===== software grid barrier =====
__device__ __forceinline__ void grid_barrier() {
    __syncthreads();
    if (threadIdx.x == 0) {
        __threadfence();
        unsigned gen = g_bar_gen;
        if (atomicAdd(&g_bar_count, 1u) == NBLK - 1) {
            atomicExch(&g_bar_count, 0u);
            __threadfence();
            g_bar_gen = gen + 1u;
        } else {
            while (g_bar_gen == gen) __nanosleep(32);
        }
        __threadfence();
    }
    __syncthreads();
}

// ===== blob packing =====
__device__ void pack_blob_fused(const float* __restrict__ W, unsigned char* __restrict__ blob,
                                int gt, int gN) {
    for (int u = gt; u < 1536 * 32; u += gN) {
        int nw = u >> 5, kc = u & 31;
        const float* wp = W + (size_t)nw * 512 + kc * 16;
        __align__(16) __nv_bfloat16 sp[2][16];
        #pragma unroll
        for (int i = 0; i < 16; i++) split2(wp[i], sp[0][i], sp[1][i]);
        int g = nw >> 9, h = nw & 511, nt = h >> 5, hl = h & 31;
        int pr = hl * 3 + g;
        #pragma unroll
        for (int p = 0; p < 4; p++) {
            int vc = p * 32 + kc;
            unsigned char* d = blob + ((size_t)(nt * NVC + vc) * 96 + pr) * 32;
            const uint4* s4 = reinterpret_cast<const uint4*>(sp[p & 1]);
            *reinterpret_cast<uint4*>(d)      = s4[0];
            *reinterpret_cast<uint4*>(d + 16) = s4[1];
        }
    }
}
__device__ void pack_blob_out(const float* __restrict__ W, unsigned char* __restrict__ blob,
                              int gt, int gN) {
    for (int u = gt; u < 512 * 32; u += gN) {
        int n = u >> 5, kc = u & 31;
        const float* wp = W + (size_t)n * 512 + kc * 16;
        __align__(16) __nv_bfloat16 sp[2][16];
        #pragma unroll
        for (int i = 0; i < 16; i++) split2(wp[i], sp[0][i], sp[1][i]);
        int nt = n >> 6, nl = n & 63;
        #pragma unroll
        for (int p = 0; p < 4; p++) {
            int vc = p * 32 + kc;
            unsigned char* d = blob + ((size_t)(nt * NVC + vc) * 64 + nl) * 32;
            const uint4* s4 = reinterpret_cast<const uint4*>(sp[p & 1]);
            *reinterpret_cast<uint4*>(d)      = s4[0];
            *reinterpret_cast<uint4*>(d + 16) = s4[1];
        }
    }
}

// ===== fused layer stage: dual gemm (gi,gh) 64m x 96n + in-block GRU combine =====
__device__ void layer_stage(const __nv_bfloat16* __restrict__ Ax, bool useWin, int slot,
                            const __nv_bfloat16* __restrict__ Ah,
                            const unsigned char* __restrict__ Bi,
                            const unsigned char* __restrict__ Bh,
                            const float* __restrict__ bih, const float* __restrict__ bhh,
                            const float* __restrict__ Hprev, float* __restrict__ Hout,
                            __nv_bfloat16* __restrict__ Hsplit) {
    const int tid = threadIdx.x, bx = blockIdx.x;
    const int mt = bx >> 4, nt = bx & 15;
    const int m0 = mt * 64;
    __nv_bfloat16* sA = (__nv_bfloat16*)smem_raw;             // [2 buf][2 role][64][32]
    __nv_bfloat16* sB = (__nv_bfloat16*)(smem_raw + 16384);   // [2 buf][2 role][96][32]

    const int warp = tid >> 5, lane = tid & 31;
    const int role = warp >> 3;            // 0: gi, 1: gh
    const int w8 = warp & 7;
    const int mpart = w8 >> 1, npart = w8 & 1;

    // ---- loaders (R12 structure) ----
    const int roleA = tid >> 8, rowA = (tid >> 2) & 63, kuA = tid & 3;
    const __nv_bfloat16* aBase;
    if (roleA == 0) {
        int m = m0 + rowA;
        int tok = useWin ? win_decode(g_winner[slot][m]) : 0;
        aBase = useWin ? (Ax + (size_t)tok * 512) : (Ax + (size_t)m * 512);
    } else {
        aBase = Ah + (size_t)(m0 + rowA) * 512;
    }
    const int aSt = roleA * 2048 + rowA * 32 + ((kuA ^ ((rowA >> 1) & 3)) * 8);
    const int roleB1 = (tid >= 384) ? 1 : 0;
    const int rv1 = tid - roleB1 * 384;
    const int rowB1 = rv1 >> 2, kuB1 = rv1 & 3;
    const unsigned char* bBase1 = (roleB1 ? Bh : Bi) + (size_t)nt * NVC * 3072;
    const int bSt1 = roleB1 * 3072 + rowB1 * 32 + ((kuB1 ^ ((rowB1 >> 1) & 3)) * 8);
    const bool hasU2 = (tid < 256);
    const int rv2 = tid + 128;
    const int rowB2 = rv2 >> 2, kuB2 = rv2 & 3;
    const unsigned char* bBase2 = Bh + (size_t)nt * NVC * 3072;
    const int bSt2 = 3072 + rowB2 * 32 + ((kuB2 ^ ((rowB2 >> 1) & 3)) * 8);

    float acc[6][4];
    #pragma unroll
    for (int j = 0; j < 6; j++)
        #pragma unroll
        for (int q = 0; q < 4; q++) acc[j][q] = 0.f;

    uint32_t sAu = smem_u32(sA), sBu = smem_u32(sB);
    const int ar = mpart * 16 + (lane & 15);
    const int a_half = lane >> 4;
    const int br_base = npart * 48 + (lane & 7) + ((lane >> 4) << 3);
    const int b_half = (lane >> 3) & 1;

    uint4 pf0, pf1, pf2;
    {   // prologue vb=0
        int vcA = (kuA >> 1);
        int sA2 = PA_of(vcA >> 5);
        pf0 = *reinterpret_cast<const uint4*>(aBase + sA2 * PLANE + (vcA & 31) * 16 + (kuA & 1) * 8);
        int vc1 = (kuB1 >> 1);
        pf1 = *reinterpret_cast<const uint4*>(bBase1 + (size_t)vc1 * 3072 + rowB1 * 32 + (kuB1 & 1) * 16);
        if (hasU2) {
            int vc2 = (kuB2 >> 1);
            pf2 = *reinterpret_cast<const uint4*>(bBase2 + (size_t)vc2 * 3072 + rowB2 * 32 + (kuB2 & 1) * 16);
        }
    }

    #pragma unroll 2
    for (int vb = 0; vb < NVB; vb++) {
        const int buf = vb & 1;
        *reinterpret_cast<uint4*>(sA + buf * 4096 + aSt) = pf0;
        *reinterpret_cast<uint4*>(sB + buf * 6144 + bSt1) = pf1;
        if (hasU2) *reinterpret_cast<uint4*>(sB + buf * 6144 + bSt2) = pf2;
        __syncthreads();

        if (vb + 1 < NVB) {
            int vn = (vb + 1) * 2;
            int vcA = vn + (kuA >> 1);
            int sA2 = PA_of(vcA >> 5);
            pf0 = *reinterpret_cast<const uint4*>(aBase + sA2 * PLANE + (vcA & 31) * 16 + (kuA & 1) * 8);
            int vc1 = vn + (kuB1 >> 1);
            pf1 = *reinterpret_cast<const uint4*>(bBase1 + (size_t)vc1 * 3072 + rowB1 * 32 + (kuB1 & 1) * 16);
            if (hasU2) {
                int vc2 = vn + (kuB2 >> 1);
                pf2 = *reinterpret_cast<const uint4*>(bBase2 + (size_t)vc2 * 3072 + rowB2 * 32 + (kuB2 & 1) * 16);
            }
        }

        #pragma unroll
        for (int kc2 = 0; kc2 < 2; kc2++) {
            uint32_t aF[4];
            {
                int ua = kc2 * 2 + a_half;
                int up = ua ^ ((ar >> 1) & 3);
                ldsm4(aF, sAu + (buf * 4096 + role * 2048 + ar * 32 + up * 8) * 2);
            }
            uint32_t bF[3][4];
            #pragma unroll
            for (int bt = 0; bt < 3; bt++) {
                int rb = br_base + bt * 16;
                int ub = kc2 * 2 + b_half;
                int up = ub ^ ((rb >> 1) & 3);
                ldsm4(bF[bt], sBu + (buf * 6144 + role * 3072 + rb * 32 + up * 8) * 2);
            }
            #pragma unroll
            for (int bt = 0; bt < 3; bt++) {
                mma_bf16(acc[bt * 2 + 0], aF, &bF[bt][0]);
                mma_bf16(acc[bt * 2 + 1], aF, &bF[bt][2]);
            }
        }
    }

    // ---- epilogue: two half-m passes, combine in-block ----
    float* stg = (float*)smem_raw;   // [2 role][32][96] = 24KB
    #pragma unroll 1
    for (int ph = 0; ph < 2; ph++) {
        __syncthreads();
        if ((mpart >> 1) == ph) {
            int ml = (mpart & 1) * 16 + (lane >> 2);
            #pragma unroll
            for (int j = 0; j < 6; j++) {
                int col = npart * 48 + j * 8 + (lane & 3) * 2;
                stg[role * 3072 + ml * 96 + col]     = acc[j][0];
                stg[role * 3072 + ml * 96 + col + 1] = acc[j][1];
                stg[role * 3072 + (ml + 8) * 96 + col]     = acc[j][2];
                stg[role * 3072 + (ml + 8) * 96 + col + 1] = acc[j][3];
            }
        }
        __syncthreads();
        #pragma unroll
        for (int q = 0; q < 2; q++) {
            int e = tid + q * 512;
            int ml = e >> 5, hl = e & 31;
            int m = m0 + ph * 32 + ml;
            int h = nt * 32 + hl;
            float ir  = stg[ml * 96 + hl * 3 + 0] + bih[h];
            float iz  = stg[ml * 96 + hl * 3 + 1] + bih[512 + h];
            float in_ = stg[ml * 96 + hl * 3 + 2] + bih[1024 + h];
            float hr  = stg[3072 + ml * 96 + hl * 3 + 0] + bhh[h];
            float hz  = stg[3072 + ml * 96 + hl * 3 + 1] + bhh[512 + h];
            float hn  = stg[3072 + ml * 96 + hl * 3 + 2] + bhh[1024 + h];
            float r = 1.f / (1.f + expf(-(ir + hr)));
            float z = 1.f / (1.f + expf(-(iz + hz)));
            float n = tanhf(in_ + r * hn);
            float hout = (1.f - z) * n + z * Hprev[(size_t)m * 512 + h];
            Hout[(size_t)m * 512 + h] = hout;
            __nv_bfloat16 s0, s1;
            split2(hout, s0, s1);
            int idx = m * 512 + h;
            Hsplit[idx] = s0;
            Hsplit[PLANE + idx] = s1;
        }
    }
    __syncthreads();
}

// ===== out stage: logits gemm 32m x 64n + bias + gumbel argmax atomics =====
__device__ void out_stage(const __nv_bfloat16* __restrict__ Abase,
                          const float* __restrict__ bout,
                          float* __restrict__ out, int t, int wslot) {
    const int tid = threadIdx.x, bx = blockIdx.x;
    const int warp = tid >> 5, lane = tid & 31;
    const int mpart = warp >> 3, npart = warp & 7;
    const int omt = bx >> 3, ont = bx & 7;
    const int m0 = omt * 32, n0 = ont * 64;
    __nv_bfloat16* sA = (__nv_bfloat16*)smem_raw;            // [2][32][32]
    __nv_bfloat16* sB = (__nv_bfloat16*)(smem_raw + 4096);   // [2][64][32]

    const unsigned char* bBase = g_blob_out + (size_t)ont * NVC * 2048;

    const bool ldA = (tid < 128);
    const bool ldB = (!ldA && tid < 384);
    int l0r = 0, l0u = 0;
    const __nv_bfloat16* aSrc = nullptr;
    if (ldA) {
        l0r = tid >> 2; l0u = tid & 3;
        aSrc = Abase + (size_t)(m0 + l0r) * 512;
    } else if (ldB) {
        int bu = tid - 128; l0r = bu >> 2; l0u = bu & 3;
    }
    const int st0 = l0r * 32 + ((l0u ^ ((l0r >> 1) & 3)) * 8);

    float acc[4] = {0.f, 0.f, 0.f, 0.f};

    uint32_t sAu = smem_u32(sA), sBu = smem_u32(sB);
    const int ar = mpart * 16 + (lane & 15);
    const int a_half = lane >> 4;
    const int lq = lane & 15;
    const int brq = npart * 8 + (lq & 7);
    const int b_half = lq >> 3;

    uint4 pf0;
    if (ldA) {
        int vc = (l0u >> 1);
        int s = PA_of(vc >> 5);
        pf0 = *reinterpret_cast<const uint4*>(aSrc + s * PLANE + (vc & 31) * 16 + (l0u & 1) * 8);
    } else if (ldB) {
        int vc = (l0u >> 1);
        pf0 = *reinterpret_cast<const uint4*>(bBase + (size_t)vc * 2048 + l0r * 32 + (l0u & 1) * 16);
    }

    #pragma unroll 2
    for (int vb = 0; vb < NVB; vb++) {
        const int buf = vb & 1;
        if (ldA) *reinterpret_cast<uint4*>(sA + buf * 1024 + st0) = pf0;
        else if (ldB) *reinterpret_cast<uint4*>(sB + buf * 2048 + st0) = pf0;
        __syncthreads();

        if (vb + 1 < NVB) {
            int vn = (vb + 1) * 2;
            int vc = vn + (l0u >> 1);
            if (ldA) {
                int s = PA_of(vc >> 5);
                pf0 = *reinterpret_cast<const uint4*>(aSrc + s * PLANE + (vc & 31) * 16 + (l0u & 1) * 8);
            } else if (ldB) {
                pf0 = *reinterpret_cast<const uint4*>(bBase + (size_t)vc * 2048 + l0r * 32 + (l0u & 1) * 16);
            }
        }

        #pragma unroll
        for (int kc2 = 0; kc2 < 2; kc2++) {
            uint32_t aF[4];
            {
                int ua = kc2 * 2 + a_half;
                int up = ua ^ ((ar >> 1) & 3);
                ldsm4(aF, sAu + (buf * 1024 + ar * 32 + up * 8) * 2);
            }
            uint32_t bF[2];
            {
                int ub = kc2 * 2 + b_half;
                int up = ub ^ ((brq >> 1) & 3);
                ldsm2(bF, sBu + (buf * 2048 + brq * 32 + up * 8) * 2);
            }
            mma_bf16(acc, aF, bF);
        }
    }

    // epilogue: bias, write logits, gumbel argmax atomics
    const int row0 = m0 + mpart * 16 + (lane >> 2);
    const int col0 = n0 + npart * 8 + (lane & 3) * 2;
    const float b0 = bout[col0], b1 = bout[col0 + 1];
    float v00 = acc[0] + b0, v01 = acc[1] + b1;
    float v10 = acc[2] + b0, v11 = acc[3] + b1;
    float* o0 = out + (size_t)row0 * (Tdim * NCdim) + (size_t)t * NCdim + col0;
    float* o1 = out + (size_t)(row0 + 8) * (Tdim * NCdim) + (size_t)t * NCdim + col0;
    *reinterpret_cast<float2*>(o0) = make_float2(v00, v01);
    *reinterpret_cast<float2*>(o1) = make_float2(v10, v11);

    unsigned key0 = g_key0[t], key1 = g_key1[t];
    #pragma unroll
    for (int rr = 0; rr < 2; rr++) {
        int row = row0 + rr * 8;
        float va = (rr ? v10 : v00) + gumbel_of(key0, key1, (unsigned)(row * 512 + col0));
        float vb = (rr ? v11 : v01) + gumbel_of(key0, key1, (unsigned)(row * 512 + col0 + 1));
        ull ka = ((ull)fkey(va) << 32) | (ull)(511 - col0);
        ull kb = ((ull)fkey(vb) << 32) | (ull)(511 - (col0 + 1));
        ull kr = (ka >= kb) ? ka : kb;
        #pragma unroll
        for (int o = 1; o <= 2; o <<= 1) {
            ull other = __shfl_xor_sync(0xffffffffu, kr, o);
            if (other > kr) kr = other;
        }
        if ((lane & 3) == 0) atomicMax(&g_winner[wslot][row], kr);
    }
    __syncthreads();
}

// ===== main persistent kernel =====
__global__ void __launch_bounds__(NTHR, 1)
prior_mma(const float* __restrict__ note, const float* __restrict__ genre,
          const float* __restrict__ Whid, const float* __restrict__ bhid,
          const float* __restrict__ emb,
          const float* __restrict__ Wih1, const float* __restrict__ Whh1,
          const float* __restrict__ bih1, const float* __restrict__ bhh1,
          const float* __restrict__ Wih2, const float* __restrict__ Whh2,
          const float* __restrict__ bih2, const float* __restrict__ bhh2,
          const float* __restrict__ Wout, const float* __restrict__ bout,
          float* __restrict__ out, float* __restrict__ tokout) {
    const int tid = threadIdx.x, bx = blockIdx.x;
    const int gt = bx * NTHR + tid;
    const int gN = NBLK * NTHR;

    // ---------- init ----------
    {
        if (gt < Tdim) {
            unsigned o0, o1;
            threefry2x32(0u, 42u, 0u, (unsigned)gt, o0, o1);
            g_key0[gt] = o0; g_key1[gt] = o1;
        }
        if (gt < Bdim) {
            g_winner[0][gt] = 0ull;
            g_winner[1][gt] = 511ull;   // decodes to tok=0 for step 0
        }

        pack_blob_fused(Wih1, g_blob_ih1, gt, gN);
        pack_blob_fused(Whh1, g_blob_hh1, gt, gN);
        pack_blob_fused(Wih2, g_blob_ih2, gt, gN);
        pack_blob_fused(Whh2, g_blob_hh2, gt, gN);
        pack_blob_out(Wout, g_blob_out, gt, gN);

        for (int idx = gt; idx < PLANE; idx += gN) {
            __nv_bfloat16 s0, s1;
            split2(emb[idx], s0, s1);
            g_embsplit[idx] = s0;
            g_embsplit[PLANE + idx] = s1;
        }

        float* sInit = (float*)smem_raw;
        for (int r = 0; r < Bdim / NBLK; r++) {
            int b = bx * (Bdim / NBLK) + r;
            for (int i = tid; i < SKELdim; i += NTHR) sInit[i] = note[b * SKELdim + i];
            for (int i = tid; i < GENdim; i += NTHR) sInit[SKELdim + i] = genre[b * GENdim + i];
            __syncthreads();
            for (int j = tid; j < Hdim; j += NTHR) {
                const float* w = Whid + (size_t)j * (SKELdim + GENdim);
                float acc = 0.f;
                #pragma unroll 8
                for (int k = 0; k < SKELdim + GENdim; k++) acc = fmaf(sInit[k], w[k], acc);
                acc += bhid[j];
                int idx = b * Hdim + j;
                g_h1[0][idx] = acc;
                __nv_bfloat16 s0, s1;
                split2(acc, s0, s1);
                g_h1s[0][idx] = s0;
                g_h1s[0][PLANE + idx] = s1;
            }
            __syncthreads();
        }
    }
    grid_barrier();

    for (int t = 0; t < Tdim; t++) {
        const int rp = t & 1, wp = rp ^ 1;
        const int rslot = (t + 1) & 1;   // winner slot holding sample of step t-1

        if (t > 0 && bx == 0 && tokout) {
            tokout[(size_t)tid * Tdim + (t - 1)] = (float)win_decode(g_winner[rslot][tid]);
        }

        // ---- stage 1: layer1 dual gemm + combine -> h1[wp] ----
        layer_stage(g_embsplit, true, rslot,
                    g_h1s[rp], g_blob_ih1, g_blob_hh1,
                    bih1, bhh1, g_h1[rp], g_h1[wp], g_h1s[wp]);
        grid_barrier();

        // ---- stage 2: layer2 dual gemm + combine -> h2[wp] (+ winner slot reset) ----
        if (bx == 1 && tid < 512) g_winner[rslot][tid] = 0ull;
        layer_stage(g_h1s[wp], false, 0,
                    (t == 0) ? g_h1s[wp] : g_h2s[rp],
                    g_blob_ih2, g_blob_hh2,
                    bih2, bhh2,
                    (t == 0) ? g_h1[wp] : g_h2[rp],
                    g_h2[wp], g_h2s[wp]);
        grid_barrier();

        // ---- stage 3: out gemm + gumbel argmax -> winner[t&1] ----
        out_stage(g_h2s[wp], bout, out, t, t & 1);
        grid_barrier();
    }

    if (bx == 0 && tokout) {
        tokout[(size_t)tid * Tdim + (Tdim - 1)] = (float)win_decode(g_winner[1][tid]);
    }
}

// ===== launch: ONE graph node =====
extern "C" void kernel_launch(void* const* d_in, const int* in_sizes, int n_in,
                              void* d_out, int out_size) {
    const float* note  = (const float*)d_in[1];
    const float* genre = (const float*)d_in[2];
    const float* W_hid = (const float*)d_in[3];
    const float* b_hid = (const float*)d_in[4];
    const float* emb   = (const float*)d_in[5];
    const float* W_ih1 = (const float*)d_in[6];
    const float* W_hh1 = (const float*)d_in[7];
    const float* b_ih1 = (const float*)d_in[8];
    const float* b_hh1 = (const float*)d_in[9];
    const float* W_ih2 = (const float*)d_in[10];
    const float* W_hh2 = (const float*)d_in[11];
    const float* b_ih2 = (const float*)d_in[12];
    const float* b_hh2 = (const float*)d_in[13];
    const float* W_out = (const float*)d_in[14];
    const float* b_out = (const float*)d_in[15];

    float* out = (float*)d_out;
    const long long need = (long long)Bdim * Tdim * NCdim + (long long)Bdim * Tdim;
    float* tokout = ((long long)out_size >= need) ? (out + (size_t)Bdim * Tdim * NCdim) : nullptr;

    prior_mma<<<NBLK, NTHR>>>(note, genre, W_hid, b_hid, emb,
                              W_ih1, W_hh1, b_ih1, b_hh1,
                              W_ih2, W_hh2, b_ih2, b_hh2,
                              W_out, b_out, out, tokout);
}